// round 10
// baseline (speedup 1.0000x reference)
#include <cuda_runtime.h>
#include <cuda_fp16.h>
#include <cstdint>
#include <cstddef>

#define N_NODES 12288
#define F 128
#define BM 96
#define BK 64
#define KSPLIT 8
#define KLEN (N_NODES / KSPLIT)     // 1536
#define KSTAGES (KLEN / BK)         // 24
#define TILES_M (N_NODES / BM)      // 128
#define GRID (TILES_M * KSPLIT)     // 1024
#define THREADS 384

#define A_BYTES (BM * 128)
#define ST_A2   (2 * A_BYTES)
#define B_BYTES (128 * 128)
#define STAGE_BYTES (ST_A2 + B_BYTES)
#define SMEM_TOTAL  (2 * STAGE_BYTES)   // 81920

#define PLANE ((size_t)N_NODES * F)
#define SLICE (2 * PLANE)

// combine smem layout: A tiles (sign/edge reused) 4x8KB, B tiles 2 gemms x 4x16KB
#define CB_A(st, pt)    ((uint32_t)(((st) * 2 + (pt)) * 8192))
#define CB_B(g, st, pt) ((uint32_t)(32768 + (g) * 65536 + ((st) * 2 + (pt)) * 16384))
#define CB_SMEM 163840

// Scratch
__device__ float g_S[(size_t)KSPLIT * 2 * N_NODES * F];   // ~101 MB partial planes
__device__ uint4 g_fB[(size_t)(N_NODES / BK) * B_BYTES / 16];
__device__ float g_c[F];
__device__ float g_b2[F];
__device__ uint4 g_WB[131072 / 16];   // [gemm][stage][hi/lo] 16KB W tiles, B-format

// ---------------------------------------------------------------------------
// helpers
// ---------------------------------------------------------------------------
__device__ __forceinline__ uint32_t smem_u32(const void* p) {
    uint32_t a;
    asm("{ .reg .u64 t; cvta.to.shared.u64 t, %1; cvt.u32.u64 %0, t; }"
        : "=r"(a) : "l"(p));
    return a;
}

__device__ __forceinline__ uint32_t pack_h2(float lo, float hi) {
    __half2 h = __floats2half2_rn(lo, hi);
    return *(uint32_t*)&h;
}

__device__ __forceinline__ float sgnf(float v) {
    return (v > 0.f ? 1.f : 0.f) - (v < 0.f ? 1.f : 0.f);
}

#define SWX(off) ((off) ^ (((off) >> 3) & 0x70))

#define CP_ASYNC16(dst_u32, src) \
    asm volatile("cp.async.cg.shared.global [%0], [%1], 16;" \
                 :: "r"(dst_u32), "l"(src) : "memory")
#define CP_COMMIT() asm volatile("cp.async.commit_group;" ::: "memory")
#define CP_WAIT0()  asm volatile("cp.async.wait_group 0;" ::: "memory")

#define LDSM_X4(r0, r1, r2, r3, addr) \
    asm volatile("ldmatrix.sync.aligned.m8n8.x4.shared.b16 {%0,%1,%2,%3}, [%4];" \
                 : "=r"(r0), "=r"(r1), "=r"(r2), "=r"(r3) : "r"(addr))

__device__ __forceinline__ void mma_f16(float* d, const uint32_t* a,
                                        uint32_t b0, uint32_t b1) {
    asm volatile(
        "mma.sync.aligned.m16n8k16.row.col.f32.f16.f16.f32 "
        "{%0,%1,%2,%3}, {%4,%5,%6,%7}, {%8,%9}, {%0,%1,%2,%3};\n"
        : "+f"(d[0]), "+f"(d[1]), "+f"(d[2]), "+f"(d[3])
        : "r"(a[0]), "r"(a[1]), "r"(a[2]), "r"(a[3]), "r"(b0), "r"(b1));
}

// ---------------------------------------------------------------------------
// Tiny prepass kernels
// ---------------------------------------------------------------------------
__global__ void zero_c_kernel() { g_c[threadIdx.x] = 0.f; }

__global__ __launch_bounds__(128)
void colsum_kernel(const float* __restrict__ feats) {
    const int t = threadIdx.x;
    const int r0 = blockIdx.x * 128;
    float s = 0.f;
#pragma unroll 4
    for (int r = 0; r < 128; ++r)
        s += feats[(size_t)(r0 + r) * F + t];
    atomicAdd(&g_c[t], s);
}

// b2 = nb + c@(Wtop+Wbot)/2 ; build hi/lo fp16 swizzled B-format tiles of
// Wd=(Wtop-Wbot)/2 (gemm 0) and We=edge_weight (gemm 1).
__global__ __launch_bounds__(128)
void wtrans_kernel(const float* __restrict__ node_weight,
                   const float* __restrict__ node_bias,
                   const float* __restrict__ edge_weight) {
    const int n = threadIdx.x;
    float b = node_bias[n];
    char* WB = (char*)g_WB;
#pragma unroll 4
    for (int k = 0; k < 128; ++k) {
        const float wt = node_weight[(size_t)k * F + n];
        const float wb_ = node_weight[(size_t)(k + 128) * F + n];
        const float wd = 0.5f * (wt - wb_);
        b += g_c[k] * 0.5f * (wt + wb_);
        const float we = edge_weight[(size_t)k * F + n];
        const int st = k >> 6;
        const uint32_t off = SWX((uint32_t)(n * 128 + (k & 63) * 2));
        __half hd = __float2half(wd);
        __half he = __float2half(we);
        *(__half*)(WB + (size_t)(st * 2 + 0) * 16384 + off) = hd;
        *(__half*)(WB + (size_t)(st * 2 + 1) * 16384 + off) = __float2half(wd - __half2float(hd));
        *(__half*)(WB + (size_t)(4 + st * 2 + 0) * 16384 + off) = he;
        *(__half*)(WB + (size_t)(4 + st * 2 + 1) * 16384 + off) = __float2half(we - __half2float(he));
    }
    g_b2[n] = b;
}

// pre-swizzled fp16 featsT tiles (grid (192,4) for shorter latency chains)
__global__ __launch_bounds__(256)
void prep_feats(const float* __restrict__ feats) {
    const int s = blockIdx.x;
    const int t = threadIdx.x;
    const int n = t >> 1;
    const int kh = (t & 1) * 32;
    const int jb = blockIdx.y * 8;
    uint32_t* out = (uint32_t*)g_fB + (size_t)s * (B_BYTES / 4);
    const float* src = feats + (size_t)(s * BK + kh) * F + n;
#pragma unroll
    for (int j = jb; j < jb + 8; j += 2) {
        const float v0 = src[(size_t)j * F];
        const float v1 = src[(size_t)(j + 1) * F];
        const uint32_t off = (uint32_t)(n * 128 + (kh + j) * 2);
        out[SWX(off) >> 2] = pack_h2(v0, v1);
    }
}

// ---------------------------------------------------------------------------
// Main kernel (unchanged from R9): split-K x8, BM=96, 12 warps (6m x 2n).
// ---------------------------------------------------------------------------
__global__ __launch_bounds__(THREADS, 1)
void spmm2_f16(const float* __restrict__ node_adj,
               const float* __restrict__ edge_adj) {
    extern __shared__ char smem[];
    const uint32_t sb = smem_u32(smem);
    const int tid  = threadIdx.x;
    const int wid  = tid >> 5;
    const int lane = tid & 31;
    const int M0     = (blockIdx.x % TILES_M) * BM;
    const int kslice = blockIdx.x / TILES_M;
    const size_t K0  = (size_t)kslice * KLEN;

    const int cm = tid >> 2;
    const int kq = tid & 3;
    const float* nrow = node_adj + (size_t)(M0 + cm) * N_NODES + K0 + kq * 16;
    const float* erow = edge_adj + (size_t)(M0 + cm) * N_NODES + K0 + kq * 16;
    const uint32_t csts0 = SWX((uint32_t)(cm * 128 + kq * 32));
    const uint32_t csts1 = SWX((uint32_t)(cm * 128 + kq * 32 + 16));

    const int wm = (wid % 6) * 16;
    const int wn = (wid / 6) * 64;
    const uint32_t arow = wm + (lane & 15);
    const uint32_t abase = arow * 128 + (lane >> 4) * 16;
    const uint32_t axor = (arow & 7) << 4;
    uint32_t bbase[4], bxor[4];
#pragma unroll
    for (int np = 0; np < 4; ++np) {
        const uint32_t brow = wn + np * 16 + ((lane >> 4) << 3) + (lane & 7);
        bbase[np] = brow * 128 + ((lane >> 3) & 1) * 16;
        bxor[np]  = (brow & 7) << 4;
    }

    float acc[2][8][4];
#pragma unroll
    for (int p = 0; p < 2; ++p)
#pragma unroll
        for (int nt = 0; nt < 8; ++nt)
#pragma unroll
            for (int c = 0; c < 4; ++c) acc[p][nt][c] = 0.f;

    const char* fB = (const char*)g_fB + (size_t)(kslice * KSTAGES) * B_BYTES;

    if (tid < 256) {
        const uint32_t dst = sb + ST_A2 + tid * 64;
        const char* src = fB + tid * 64;
#pragma unroll
        for (int q = 0; q < 4; ++q) CP_ASYNC16(dst + q * 16, src + q * 16);
    }
    CP_COMMIT();
    {
        float4 n0 = *(const float4*)(nrow);
        float4 n1 = *(const float4*)(nrow + 4);
        float4 n2 = *(const float4*)(nrow + 8);
        float4 n3 = *(const float4*)(nrow + 12);
        float4 e0 = *(const float4*)(erow);
        float4 e1 = *(const float4*)(erow + 4);
        float4 e2 = *(const float4*)(erow + 8);
        float4 e3 = *(const float4*)(erow + 12);
        uint4 S0, S1, E0, E1;
        S0 = make_uint4(pack_h2(sgnf(n0.x), sgnf(n0.y)), pack_h2(sgnf(n0.z), sgnf(n0.w)),
                        pack_h2(sgnf(n1.x), sgnf(n1.y)), pack_h2(sgnf(n1.z), sgnf(n1.w)));
        S1 = make_uint4(pack_h2(sgnf(n2.x), sgnf(n2.y)), pack_h2(sgnf(n2.z), sgnf(n2.w)),
                        pack_h2(sgnf(n3.x), sgnf(n3.y)), pack_h2(sgnf(n3.z), sgnf(n3.w)));
        E0 = make_uint4(pack_h2(e0.x, e0.y), pack_h2(e0.z, e0.w),
                        pack_h2(e1.x, e1.y), pack_h2(e1.z, e1.w));
        E1 = make_uint4(pack_h2(e2.x, e2.y), pack_h2(e2.z, e2.w),
                        pack_h2(e3.x, e3.y), pack_h2(e3.z, e3.w));
        *(uint4*)(smem + 0 * A_BYTES + csts0) = S0;
        *(uint4*)(smem + 0 * A_BYTES + csts1) = S1;
        *(uint4*)(smem + 1 * A_BYTES + csts0) = E0;
        *(uint4*)(smem + 1 * A_BYTES + csts1) = E1;
    }
    CP_WAIT0();
    __syncthreads();

    float4 nv[4], ev[4];

#pragma unroll 1
    for (int s = 0; s < KSTAGES; ++s) {
        const uint32_t cur = (uint32_t)(s & 1) * STAGE_BYTES;
        const uint32_t nxt = (uint32_t)((s + 1) & 1) * STAGE_BYTES;

        if (s + 1 < KSTAGES) {
            if (tid < 256) {
                const uint32_t dst = sb + nxt + ST_A2 + tid * 64;
                const char* src = fB + (size_t)(s + 1) * B_BYTES + tid * 64;
#pragma unroll
                for (int q = 0; q < 4; ++q) CP_ASYNC16(dst + q * 16, src + q * 16);
            }
            CP_COMMIT();
            const size_t k0 = (size_t)(s + 1) * BK;
#pragma unroll
            for (int i = 0; i < 4; ++i) {
                nv[i] = *(const float4*)(nrow + k0 + i * 4);
                ev[i] = *(const float4*)(erow + k0 + i * 4);
            }
        }

        const uint32_t sbA = sb + cur;
        const uint32_t sbB = sb + cur + ST_A2;
#pragma unroll
        for (int ks = 0; ks < 4; ++ks) {
            uint32_t b[4][4];
#pragma unroll
            for (int np = 0; np < 4; ++np)
                LDSM_X4(b[np][0], b[np][1], b[np][2], b[np][3],
                        sbB + ((bbase[np] + ks * 32) ^ bxor[np]));
#pragma unroll
            for (int p = 0; p < 2; ++p) {
                uint32_t a[4];
                LDSM_X4(a[0], a[1], a[2], a[3],
                        sbA + p * A_BYTES + ((abase + ks * 32) ^ axor));
#pragma unroll
                for (int np = 0; np < 4; ++np) {
                    mma_f16(acc[p][np * 2],     a, b[np][0], b[np][1]);
                    mma_f16(acc[p][np * 2 + 1], a, b[np][2], b[np][3]);
                }
            }
        }

        if (s + 1 < KSTAGES) {
            char* bp = smem + ((s + 1) & 1) * STAGE_BYTES;
            uint4 S0, S1, E0, E1;
            S0 = make_uint4(pack_h2(sgnf(nv[0].x), sgnf(nv[0].y)), pack_h2(sgnf(nv[0].z), sgnf(nv[0].w)),
                            pack_h2(sgnf(nv[1].x), sgnf(nv[1].y)), pack_h2(sgnf(nv[1].z), sgnf(nv[1].w)));
            S1 = make_uint4(pack_h2(sgnf(nv[2].x), sgnf(nv[2].y)), pack_h2(sgnf(nv[2].z), sgnf(nv[2].w)),
                            pack_h2(sgnf(nv[3].x), sgnf(nv[3].y)), pack_h2(sgnf(nv[3].z), sgnf(nv[3].w)));
            E0 = make_uint4(pack_h2(ev[0].x, ev[0].y), pack_h2(ev[0].z, ev[0].w),
                            pack_h2(ev[1].x, ev[1].y), pack_h2(ev[1].z, ev[1].w));
            E1 = make_uint4(pack_h2(ev[2].x, ev[2].y), pack_h2(ev[2].z, ev[2].w),
                            pack_h2(ev[3].x, ev[3].y), pack_h2(ev[3].z, ev[3].w));
            *(uint4*)(bp + 0 * A_BYTES + csts0) = S0;
            *(uint4*)(bp + 0 * A_BYTES + csts1) = S1;
            *(uint4*)(bp + 1 * A_BYTES + csts0) = E0;
            *(uint4*)(bp + 1 * A_BYTES + csts1) = E1;
            CP_WAIT0();
            __syncthreads();
        }
    }

    const int er0 = wm + (lane >> 2);
    const int ec0 = wn + (lane & 3) * 2;
#pragma unroll
    for (int p = 0; p < 2; ++p) {
        float* base = g_S + (size_t)kslice * SLICE + (size_t)p * PLANE
                    + (size_t)(M0 + er0) * F + ec0;
#pragma unroll
        for (int nt = 0; nt < 8; ++nt) {
            *(float2*)(base + nt * 8)         = make_float2(acc[p][nt][0], acc[p][nt][1]);
            *(float2*)(base + 8 * F + nt * 8) = make_float2(acc[p][nt][2], acc[p][nt][3]);
        }
    }
}

// ---------------------------------------------------------------------------
// Tensor-core combine: out = relu(Ssum_sign@Wd + b2) + Ssum_edge@We + eb
// hi/lo fp16 3-term split; 64 rows/block, 4 warps (each 16m x 128n).
// ---------------------------------------------------------------------------
__global__ __launch_bounds__(128)
void combine_tc(const float* __restrict__ edge_bias,
                float* __restrict__ out) {
    extern __shared__ char smem[];
    const uint32_t sb = smem_u32(smem);
    const int tid = threadIdx.x;
    const int wid = tid >> 5;
    const int lane = tid & 31;
    const int R0 = blockIdx.x * 64;

    // B fill: raw copy of pre-built W tiles (128 KB, layout already matches CB_B)
    {
        const char* src = (const char*)g_WB + tid * 1024;
        const uint32_t dst = sb + 32768 + tid * 1024;
#pragma unroll
        for (int q = 0; q < 64; ++q) CP_ASYNC16(dst + q * 16, src + q * 16);
        CP_COMMIT();
    }

    // A fill: sum 8 slices of plane p, split hi/lo, store swizzled
    const int ar = tid >> 1;
    const int akh = tid & 1;
    auto a_fill = [&](int p) {
        const float* src = g_S + (size_t)p * PLANE + (size_t)(R0 + ar) * F + akh * 64;
        char* Ah = smem + CB_A(akh, 0);
        char* Al = smem + CB_A(akh, 1);
#pragma unroll 4
        for (int q = 0; q < 16; ++q) {
            float4 s = *(const float4*)(src + q * 4);
#pragma unroll
            for (int sl = 1; sl < KSPLIT; ++sl) {
                float4 a = *(const float4*)(src + (size_t)sl * SLICE + q * 4);
                s.x += a.x; s.y += a.y; s.z += a.z; s.w += a.w;
            }
            const uint32_t h0 = pack_h2(s.x, s.y);
            const uint32_t h1 = pack_h2(s.z, s.w);
            const float2 f0 = __half22float2(*(const __half2*)&h0);
            const float2 f1 = __half22float2(*(const __half2*)&h1);
            const uint32_t l0 = pack_h2(s.x - f0.x, s.y - f0.y);
            const uint32_t l1 = pack_h2(s.z - f1.x, s.w - f1.y);
            const uint32_t off = SWX((uint32_t)(ar * 128 + q * 8));
            *(uint2*)(Ah + off) = make_uint2(h0, h1);
            *(uint2*)(Al + off) = make_uint2(l0, l1);
        }
    };

    // mma addressing
    const uint32_t arow = wid * 16 + (lane & 15);
    const uint32_t abase = arow * 128 + (lane >> 4) * 16;
    const uint32_t axor = (arow & 7) << 4;
    uint32_t bbase[8], bxor[8];
#pragma unroll
    for (int np = 0; np < 8; ++np) {
        const uint32_t brow = np * 16 + ((lane >> 4) << 3) + (lane & 7);
        bbase[np] = brow * 128 + ((lane >> 3) & 1) * 16;
        bxor[np]  = (brow & 7) << 4;
    }

    auto gemm = [&](int g, float (*acc)[4]) {
#pragma unroll
        for (int ks = 0; ks < 8; ++ks) {
            const int st = ks >> 2;
            const uint32_t ko = (uint32_t)(ks & 3) * 32;
            uint32_t ah[4], al[4];
            LDSM_X4(ah[0], ah[1], ah[2], ah[3], sb + CB_A(st, 0) + ((abase + ko) ^ axor));
            LDSM_X4(al[0], al[1], al[2], al[3], sb + CB_A(st, 1) + ((abase + ko) ^ axor));
#pragma unroll
            for (int np = 0; np < 8; ++np) {
                uint32_t bh[4], bl[4];
                LDSM_X4(bh[0], bh[1], bh[2], bh[3],
                        sb + CB_B(g, st, 0) + ((bbase[np] + ko) ^ bxor[np]));
                LDSM_X4(bl[0], bl[1], bl[2], bl[3],
                        sb + CB_B(g, st, 1) + ((bbase[np] + ko) ^ bxor[np]));
                mma_f16(acc[np * 2],     ah, bh[0], bh[1]);
                mma_f16(acc[np * 2 + 1], ah, bh[2], bh[3]);
                mma_f16(acc[np * 2],     ah, bl[0], bl[1]);
                mma_f16(acc[np * 2 + 1], ah, bl[2], bl[3]);
                mma_f16(acc[np * 2],     al, bh[0], bh[1]);
                mma_f16(acc[np * 2 + 1], al, bh[2], bh[3]);
            }
        }
    };

    float accN[16][4], accE[16][4];
#pragma unroll
    for (int nt = 0; nt < 16; ++nt)
#pragma unroll
        for (int c = 0; c < 4; ++c) { accN[nt][c] = 0.f; accE[nt][c] = 0.f; }

    a_fill(0);            // sign plane sums
    CP_WAIT0();
    __syncthreads();
    gemm(0, accN);        // @ Wd tiles
    __syncthreads();
    a_fill(1);            // edge plane sums
    __syncthreads();
    gemm(1, accE);        // @ We tiles

    // epilogue
    const int er = R0 + wid * 16 + (lane >> 2);
#pragma unroll
    for (int nt = 0; nt < 16; ++nt) {
        const int c = nt * 8 + (lane & 3) * 2;
        const float2 b2 = *(const float2*)(g_b2 + c);
        const float2 eb = *(const float2*)(edge_bias + c);
        out[(size_t)er * F + c]           = fmaxf(accN[nt][0] + b2.x, 0.f) + accE[nt][0] + eb.x;
        out[(size_t)er * F + c + 1]       = fmaxf(accN[nt][1] + b2.y, 0.f) + accE[nt][1] + eb.y;
        out[(size_t)(er + 8) * F + c]     = fmaxf(accN[nt][2] + b2.x, 0.f) + accE[nt][2] + eb.x;
        out[(size_t)(er + 8) * F + c + 1] = fmaxf(accN[nt][3] + b2.y, 0.f) + accE[nt][3] + eb.y;
    }
}

extern "C" void kernel_launch(void* const* d_in, const int* in_sizes, int n_in,
                              void* d_out, int out_size) {
    const float* feats       = (const float*)d_in[0];
    const float* node_adj    = (const float*)d_in[1];
    const float* edge_adj    = (const float*)d_in[2];
    const float* node_weight = (const float*)d_in[3];
    const float* node_bias   = (const float*)d_in[4];
    const float* edge_weight = (const float*)d_in[5];
    const float* edge_bias   = (const float*)d_in[6];
    float* out = (float*)d_out;

    cudaFuncSetAttribute(spmm2_f16, cudaFuncAttributeMaxDynamicSharedMemorySize, SMEM_TOTAL);
    cudaFuncSetAttribute(combine_tc, cudaFuncAttributeMaxDynamicSharedMemorySize, CB_SMEM);

    zero_c_kernel<<<1, 128>>>();
    colsum_kernel<<<96, 128>>>(feats);
    wtrans_kernel<<<1, 128>>>(node_weight, node_bias, edge_weight);
    prep_feats<<<dim3(N_NODES / BK, 4), 256>>>(feats);
    spmm2_f16<<<GRID, THREADS, SMEM_TOTAL>>>(node_adj, edge_adj);
    combine_tc<<<N_NODES / 64, 128, CB_SMEM>>>(edge_bias, out);
}

// round 11
// speedup vs baseline: 1.1526x; 1.1526x over previous
#include <cuda_runtime.h>
#include <cuda_fp16.h>
#include <cstdint>
#include <cstddef>

#define N_NODES 12288
#define F 128
#define BM 96
#define BK 64
#define KSPLIT 8
#define KLEN (N_NODES / KSPLIT)     // 1536
#define KSTAGES (KLEN / BK)         // 24
#define TILES_M (N_NODES / BM)      // 128
#define GRID (TILES_M * KSPLIT)     // 1024
#define THREADS 384

#define A_BYTES (BM * 128)
#define ST_A2   (2 * A_BYTES)
#define B_BYTES (128 * 128)
#define STAGE_BYTES (ST_A2 + B_BYTES)
#define SMEM_TOTAL  (2 * STAGE_BYTES)   // 81920

#define PLANE ((size_t)N_NODES * F)
#define SLICE (2 * PLANE)

// Scratch
__device__ float g_S[(size_t)KSPLIT * 2 * N_NODES * F];   // partial planes (~101 MB)
__device__ float g_Sum[(size_t)2 * N_NODES * F];          // summed planes (12.6 MB)
__device__ uint4 g_fB[(size_t)(N_NODES / BK) * B_BYTES / 16];
__device__ float g_cpart[96 * F];
__device__ float g_Wd[F * F];
__device__ float g_b2[F];

// ---------------------------------------------------------------------------
// helpers
// ---------------------------------------------------------------------------
__device__ __forceinline__ uint32_t smem_u32(const void* p) {
    uint32_t a;
    asm("{ .reg .u64 t; cvta.to.shared.u64 t, %1; cvt.u32.u64 %0, t; }"
        : "=r"(a) : "l"(p));
    return a;
}

__device__ __forceinline__ uint32_t pack_h2(float lo, float hi) {
    __half2 h = __floats2half2_rn(lo, hi);
    return *(uint32_t*)&h;
}

__device__ __forceinline__ float sgnf(float v) {
    return (v > 0.f ? 1.f : 0.f) - (v < 0.f ? 1.f : 0.f);
}

#define SWX(off) ((off) ^ (((off) >> 3) & 0x70))

#define CP_ASYNC16(dst_u32, src) \
    asm volatile("cp.async.cg.shared.global [%0], [%1], 16;" \
                 :: "r"(dst_u32), "l"(src) : "memory")
#define CP_COMMIT() asm volatile("cp.async.commit_group;" ::: "memory")
#define CP_WAIT0()  asm volatile("cp.async.wait_group 0;" ::: "memory")

#define LDSM_X4(r0, r1, r2, r3, addr) \
    asm volatile("ldmatrix.sync.aligned.m8n8.x4.shared.b16 {%0,%1,%2,%3}, [%4];" \
                 : "=r"(r0), "=r"(r1), "=r"(r2), "=r"(r3) : "r"(addr))

__device__ __forceinline__ void mma_f16(float* d, const uint32_t* a,
                                        uint32_t b0, uint32_t b1) {
    asm volatile(
        "mma.sync.aligned.m16n8k16.row.col.f32.f16.f16.f32 "
        "{%0,%1,%2,%3}, {%4,%5,%6,%7}, {%8,%9}, {%0,%1,%2,%3};\n"
        : "+f"(d[0]), "+f"(d[1]), "+f"(d[2]), "+f"(d[3])
        : "r"(a[0]), "r"(a[1]), "r"(a[2]), "r"(a[3]), "r"(b0), "r"(b1));
}

// ---------------------------------------------------------------------------
// Prepass kernels
// ---------------------------------------------------------------------------
// per-block column partial sums (no atomics, no zero pass)
__global__ __launch_bounds__(128)
void colsum_kernel(const float* __restrict__ feats) {
    const int t = threadIdx.x;
    const int r0 = blockIdx.x * 128;
    float s = 0.f;
#pragma unroll 4
    for (int r = 0; r < 128; ++r)
        s += feats[(size_t)(r0 + r) * F + t];
    g_cpart[blockIdx.x * F + t] = s;
}

// Wd = (Wtop - Wbot)/2 ; b2 = nb + c @ (Wtop + Wbot)/2 with c = sum of partials
__global__ __launch_bounds__(128)
void wtrans_kernel(const float* __restrict__ node_weight,
                   const float* __restrict__ node_bias) {
    __shared__ float cs[F];
    const int j = threadIdx.x;
    {
        float c = 0.f;
#pragma unroll 4
        for (int b = 0; b < 96; ++b)
            c += g_cpart[b * F + j];
        cs[j] = c;
    }
    __syncthreads();
    float b = node_bias[j];
#pragma unroll 4
    for (int k = 0; k < 128; ++k) {
        const float wt = node_weight[(size_t)k * F + j];
        const float wb = node_weight[(size_t)(k + 128) * F + j];
        g_Wd[k * F + j] = 0.5f * (wt - wb);
        b += cs[k] * 0.5f * (wt + wb);
    }
    g_b2[j] = b;
}

// pre-swizzled fp16 featsT tiles (grid (192,4))
__global__ __launch_bounds__(256)
void prep_feats(const float* __restrict__ feats) {
    const int s = blockIdx.x;
    const int t = threadIdx.x;
    const int n = t >> 1;
    const int kh = (t & 1) * 32;
    const int jb = blockIdx.y * 8;
    uint32_t* out = (uint32_t*)g_fB + (size_t)s * (B_BYTES / 4);
    const float* src = feats + (size_t)(s * BK + kh) * F + n;
#pragma unroll
    for (int j = jb; j < jb + 8; j += 2) {
        const float v0 = src[(size_t)j * F];
        const float v1 = src[(size_t)(j + 1) * F];
        const uint32_t off = (uint32_t)(n * 128 + (kh + j) * 2);
        out[SWX(off) >> 2] = pack_h2(v0, v1);
    }
}

// ---------------------------------------------------------------------------
// Main kernel (identical to R9): split-K x8, BM=96, 12 warps (6m x 2n).
// ---------------------------------------------------------------------------
__global__ __launch_bounds__(THREADS, 1)
void spmm2_f16(const float* __restrict__ node_adj,
               const float* __restrict__ edge_adj) {
    extern __shared__ char smem[];
    const uint32_t sb = smem_u32(smem);
    const int tid  = threadIdx.x;
    const int wid  = tid >> 5;
    const int lane = tid & 31;
    const int M0     = (blockIdx.x % TILES_M) * BM;
    const int kslice = blockIdx.x / TILES_M;
    const size_t K0  = (size_t)kslice * KLEN;

    const int cm = tid >> 2;
    const int kq = tid & 3;
    const float* nrow = node_adj + (size_t)(M0 + cm) * N_NODES + K0 + kq * 16;
    const float* erow = edge_adj + (size_t)(M0 + cm) * N_NODES + K0 + kq * 16;
    const uint32_t csts0 = SWX((uint32_t)(cm * 128 + kq * 32));
    const uint32_t csts1 = SWX((uint32_t)(cm * 128 + kq * 32 + 16));

    const int wm = (wid % 6) * 16;
    const int wn = (wid / 6) * 64;
    const uint32_t arow = wm + (lane & 15);
    const uint32_t abase = arow * 128 + (lane >> 4) * 16;
    const uint32_t axor = (arow & 7) << 4;
    uint32_t bbase[4], bxor[4];
#pragma unroll
    for (int np = 0; np < 4; ++np) {
        const uint32_t brow = wn + np * 16 + ((lane >> 4) << 3) + (lane & 7);
        bbase[np] = brow * 128 + ((lane >> 3) & 1) * 16;
        bxor[np]  = (brow & 7) << 4;
    }

    float acc[2][8][4];
#pragma unroll
    for (int p = 0; p < 2; ++p)
#pragma unroll
        for (int nt = 0; nt < 8; ++nt)
#pragma unroll
            for (int c = 0; c < 4; ++c) acc[p][nt][c] = 0.f;

    const char* fB = (const char*)g_fB + (size_t)(kslice * KSTAGES) * B_BYTES;

    if (tid < 256) {
        const uint32_t dst = sb + ST_A2 + tid * 64;
        const char* src = fB + tid * 64;
#pragma unroll
        for (int q = 0; q < 4; ++q) CP_ASYNC16(dst + q * 16, src + q * 16);
    }
    CP_COMMIT();
    {
        float4 n0 = *(const float4*)(nrow);
        float4 n1 = *(const float4*)(nrow + 4);
        float4 n2 = *(const float4*)(nrow + 8);
        float4 n3 = *(const float4*)(nrow + 12);
        float4 e0 = *(const float4*)(erow);
        float4 e1 = *(const float4*)(erow + 4);
        float4 e2 = *(const float4*)(erow + 8);
        float4 e3 = *(const float4*)(erow + 12);
        uint4 S0, S1, E0, E1;
        S0 = make_uint4(pack_h2(sgnf(n0.x), sgnf(n0.y)), pack_h2(sgnf(n0.z), sgnf(n0.w)),
                        pack_h2(sgnf(n1.x), sgnf(n1.y)), pack_h2(sgnf(n1.z), sgnf(n1.w)));
        S1 = make_uint4(pack_h2(sgnf(n2.x), sgnf(n2.y)), pack_h2(sgnf(n2.z), sgnf(n2.w)),
                        pack_h2(sgnf(n3.x), sgnf(n3.y)), pack_h2(sgnf(n3.z), sgnf(n3.w)));
        E0 = make_uint4(pack_h2(e0.x, e0.y), pack_h2(e0.z, e0.w),
                        pack_h2(e1.x, e1.y), pack_h2(e1.z, e1.w));
        E1 = make_uint4(pack_h2(e2.x, e2.y), pack_h2(e2.z, e2.w),
                        pack_h2(e3.x, e3.y), pack_h2(e3.z, e3.w));
        *(uint4*)(smem + 0 * A_BYTES + csts0) = S0;
        *(uint4*)(smem + 0 * A_BYTES + csts1) = S1;
        *(uint4*)(smem + 1 * A_BYTES + csts0) = E0;
        *(uint4*)(smem + 1 * A_BYTES + csts1) = E1;
    }
    CP_WAIT0();
    __syncthreads();

    float4 nv[4], ev[4];

#pragma unroll 1
    for (int s = 0; s < KSTAGES; ++s) {
        const uint32_t cur = (uint32_t)(s & 1) * STAGE_BYTES;
        const uint32_t nxt = (uint32_t)((s + 1) & 1) * STAGE_BYTES;

        if (s + 1 < KSTAGES) {
            if (tid < 256) {
                const uint32_t dst = sb + nxt + ST_A2 + tid * 64;
                const char* src = fB + (size_t)(s + 1) * B_BYTES + tid * 64;
#pragma unroll
                for (int q = 0; q < 4; ++q) CP_ASYNC16(dst + q * 16, src + q * 16);
            }
            CP_COMMIT();
            const size_t k0 = (size_t)(s + 1) * BK;
#pragma unroll
            for (int i = 0; i < 4; ++i) {
                nv[i] = *(const float4*)(nrow + k0 + i * 4);
                ev[i] = *(const float4*)(erow + k0 + i * 4);
            }
        }

        const uint32_t sbA = sb + cur;
        const uint32_t sbB = sb + cur + ST_A2;
#pragma unroll
        for (int ks = 0; ks < 4; ++ks) {
            uint32_t b[4][4];
#pragma unroll
            for (int np = 0; np < 4; ++np)
                LDSM_X4(b[np][0], b[np][1], b[np][2], b[np][3],
                        sbB + ((bbase[np] + ks * 32) ^ bxor[np]));
#pragma unroll
            for (int p = 0; p < 2; ++p) {
                uint32_t a[4];
                LDSM_X4(a[0], a[1], a[2], a[3],
                        sbA + p * A_BYTES + ((abase + ks * 32) ^ axor));
#pragma unroll
                for (int np = 0; np < 4; ++np) {
                    mma_f16(acc[p][np * 2],     a, b[np][0], b[np][1]);
                    mma_f16(acc[p][np * 2 + 1], a, b[np][2], b[np][3]);
                }
            }
        }

        if (s + 1 < KSTAGES) {
            char* bp = smem + ((s + 1) & 1) * STAGE_BYTES;
            uint4 S0, S1, E0, E1;
            S0 = make_uint4(pack_h2(sgnf(nv[0].x), sgnf(nv[0].y)), pack_h2(sgnf(nv[0].z), sgnf(nv[0].w)),
                            pack_h2(sgnf(nv[1].x), sgnf(nv[1].y)), pack_h2(sgnf(nv[1].z), sgnf(nv[1].w)));
            S1 = make_uint4(pack_h2(sgnf(nv[2].x), sgnf(nv[2].y)), pack_h2(sgnf(nv[2].z), sgnf(nv[2].w)),
                            pack_h2(sgnf(nv[3].x), sgnf(nv[3].y)), pack_h2(sgnf(nv[3].z), sgnf(nv[3].w)));
            E0 = make_uint4(pack_h2(ev[0].x, ev[0].y), pack_h2(ev[0].z, ev[0].w),
                            pack_h2(ev[1].x, ev[1].y), pack_h2(ev[1].z, ev[1].w));
            E1 = make_uint4(pack_h2(ev[2].x, ev[2].y), pack_h2(ev[2].z, ev[2].w),
                            pack_h2(ev[3].x, ev[3].y), pack_h2(ev[3].z, ev[3].w));
            *(uint4*)(bp + 0 * A_BYTES + csts0) = S0;
            *(uint4*)(bp + 0 * A_BYTES + csts1) = S1;
            *(uint4*)(bp + 1 * A_BYTES + csts0) = E0;
            *(uint4*)(bp + 1 * A_BYTES + csts1) = E1;
            CP_WAIT0();
            __syncthreads();
        }
    }

    const int er0 = wm + (lane >> 2);
    const int ec0 = wn + (lane & 3) * 2;
#pragma unroll
    for (int p = 0; p < 2; ++p) {
        float* base = g_S + (size_t)kslice * SLICE + (size_t)p * PLANE
                    + (size_t)(M0 + er0) * F + ec0;
#pragma unroll
        for (int nt = 0; nt < 8; ++nt) {
            *(float2*)(base + nt * 8)         = make_float2(acc[p][nt][0], acc[p][nt][1]);
            *(float2*)(base + 8 * F + nt * 8) = make_float2(acc[p][nt][2], acc[p][nt][3]);
        }
    }
}

// ---------------------------------------------------------------------------
// Streaming slice reduction: g_Sum = sum of 8 k-slices (both planes flat)
// ---------------------------------------------------------------------------
#define RED_GROUPS (2 * N_NODES * F / 4)   // 786432 float4 outputs
__global__ __launch_bounds__(256)
void reduce_kernel() {
    const int idx = blockIdx.x * 256 + threadIdx.x;   // grid 768 -> 196608 threads
#pragma unroll
    for (int g = 0; g < 4; ++g) {
        const size_t i = (size_t)(idx + g * 196608) * 4;
        float4 s = *(const float4*)(g_S + i);
#pragma unroll
        for (int sl = 1; sl < KSPLIT; ++sl) {
            float4 a = *(const float4*)(g_S + (size_t)sl * SLICE + i);
            s.x += a.x; s.y += a.y; s.z += a.z; s.w += a.w;
        }
        *(float4*)(g_Sum + i) = s;
    }
}

// ---------------------------------------------------------------------------
// Combine (R9 structure on pre-summed planes):
// out = relu(Ssum_sign @ Wd + b2) + Ssum_edge @ We + eb
// ---------------------------------------------------------------------------
__device__ __forceinline__ void accum_block(const float* __restrict__ W,
                                            const float* __restrict__ S,
                                            float* acc,
                                            float* Ws, float* Ss,
                                            int tid, int tx, int ty, int R0) {
#pragma unroll 1
    for (int k0 = 0; k0 < 128; k0 += 32) {
        __syncthreads();
#pragma unroll
        for (int i = 0; i < 4; ++i) {
            const int e = tid + i * 256;
            const int wrow = e >> 5;
            const int wc = (e & 31) * 4;
            *(float4*)(Ws + wrow * 128 + wc) = *(const float4*)(W + (k0 + wrow) * 128 + wc);
        }
        {
            const int srow = tid >> 3;
            const int sc = (tid & 7) * 4;
            *(float4*)(Ss + srow * 36 + sc) =
                *(const float4*)(S + (size_t)(R0 + srow) * F + k0 + sc);
        }
        __syncthreads();
#pragma unroll 8
        for (int kk = 0; kk < 32; ++kk) {
            float w[4], sv[4];
#pragma unroll
            for (int v = 0; v < 4; ++v) w[v] = Ws[kk * 128 + tx + 32 * v];
#pragma unroll
            for (int u = 0; u < 4; ++u) sv[u] = Ss[(ty + 8 * u) * 36 + kk];
#pragma unroll
            for (int u = 0; u < 4; ++u)
#pragma unroll
                for (int v = 0; v < 4; ++v)
                    acc[u * 4 + v] = fmaf(sv[u], w[v], acc[u * 4 + v]);
        }
    }
}

__global__ __launch_bounds__(256)
void combine_kernel(const float* __restrict__ edge_weight,
                    const float* __restrict__ edge_bias,
                    float* __restrict__ out) {
    __shared__ float Ws[32 * 128];
    __shared__ float Ss[32 * 36];

    const int tid = threadIdx.x;
    const int tx = tid & 31;
    const int ty = tid >> 5;
    const int R0 = blockIdx.x * 32;

    float accN[16], accE[16];
#pragma unroll
    for (int i = 0; i < 16; ++i) { accN[i] = 0.f; accE[i] = 0.f; }

    accum_block(g_Wd,        g_Sum,         accN, Ws, Ss, tid, tx, ty, R0);
    accum_block(edge_weight, g_Sum + PLANE, accE, Ws, Ss, tid, tx, ty, R0);

    float b2[4], eb[4];
#pragma unroll
    for (int v = 0; v < 4; ++v) {
        b2[v] = g_b2[tx + 32 * v];
        eb[v] = edge_bias[tx + 32 * v];
    }
#pragma unroll
    for (int u = 0; u < 4; ++u)
#pragma unroll
        for (int v = 0; v < 4; ++v) {
            const int rr = R0 + ty + 8 * u;
            const int c = tx + 32 * v;
            out[(size_t)rr * F + c] =
                fmaxf(accN[u * 4 + v] + b2[v], 0.f) + accE[u * 4 + v] + eb[v];
        }
}

extern "C" void kernel_launch(void* const* d_in, const int* in_sizes, int n_in,
                              void* d_out, int out_size) {
    const float* feats       = (const float*)d_in[0];
    const float* node_adj    = (const float*)d_in[1];
    const float* edge_adj    = (const float*)d_in[2];
    const float* node_weight = (const float*)d_in[3];
    const float* node_bias   = (const float*)d_in[4];
    const float* edge_weight = (const float*)d_in[5];
    const float* edge_bias   = (const float*)d_in[6];
    float* out = (float*)d_out;

    cudaFuncSetAttribute(spmm2_f16, cudaFuncAttributeMaxDynamicSharedMemorySize, SMEM_TOTAL);

    colsum_kernel<<<96, 128>>>(feats);
    wtrans_kernel<<<1, 128>>>(node_weight, node_bias);
    prep_feats<<<dim3(N_NODES / BK, 4), 256>>>(feats);
    spmm2_f16<<<GRID, THREADS, SMEM_TOTAL>>>(node_adj, edge_adj);
    reduce_kernel<<<768, 256>>>();
    combine_kernel<<<N_NODES / 32, 256>>>(edge_weight, edge_bias, out);
}